// round 13
// baseline (speedup 1.0000x reference)
#include <cuda_runtime.h>
#include <cuda_fp16.h>
#include <cstdint>

// Problem constants
#define KK   27
#define RR   50000
#define CIN  64
#define COUT 64
#define NIN  150000
#define NOUT 150000

#define TILE    128
#define NTILES  ((RR + TILE - 1) / TILE)      // 391
#define TPB     14                            // tiles per block
#define TPG     7                             // tiles per group (2 groups)
#define NBX     ((NTILES + TPB - 1) / TPB)    // 28
#define THREADS 512

// SMEM: W(hi) 8K, then per-group 3 stages x 32K (stage = AH 16K | AL 16K)
#define OFF_WH  0u
#define OFF_A   8192u
#define GRP_B   98304u      // 3 * 32768
#define STG_SZ  32768u
#define SMEM_BYTES (8192u + 2u * GRP_B)       // 204800

// ---- global scratch ----------------------------------------------------------
__device__ __align__(16) unsigned short g_xsplit[(size_t)NIN * 128];   // fp16 [hi64|lo64]
__device__ __align__(16) unsigned short g_wh[(size_t)KK * 4096];       // fp16 wh swizzled

// ---- helpers -------------------------------------------------------------------
__device__ __forceinline__ uint32_t smem_u32(const void* p) {
    uint32_t a;
    asm("{ .reg .u64 t; cvta.to.shared.u64 t, %1; cvt.u32.u64 %0, t; }" : "=r"(a) : "l"(p));
    return a;
}
__device__ __forceinline__ void ldm4(uint32_t addr, uint32_t& r0, uint32_t& r1,
                                     uint32_t& r2, uint32_t& r3) {
    asm volatile("ldmatrix.sync.aligned.m8n8.x4.shared.b16 {%0,%1,%2,%3}, [%4];"
                 : "=r"(r0), "=r"(r1), "=r"(r2), "=r"(r3) : "r"(addr));
}
__device__ __forceinline__ void mma_f16(float4& d,
                                        uint32_t a0, uint32_t a1, uint32_t a2, uint32_t a3,
                                        uint32_t b0, uint32_t b1) {
    asm volatile("mma.sync.aligned.m16n8k16.row.col.f32.f16.f16.f32 "
                 "{%0,%1,%2,%3}, {%4,%5,%6,%7}, {%8,%9}, {%0,%1,%2,%3};"
                 : "+f"(d.x), "+f"(d.y), "+f"(d.z), "+f"(d.w)
                 : "r"(a0), "r"(a1), "r"(a2), "r"(a3), "r"(b0), "r"(b1));
}
__device__ __forceinline__ void red4(float* p, float a, float b, float c, float d) {
    asm volatile("red.global.add.v4.f32 [%0], {%1, %2, %3, %4};"
                 :: "l"(p), "f"(a), "f"(b), "f"(c), "f"(d) : "memory");
}
__device__ __forceinline__ void bar_grp(int id) {
    asm volatile("bar.sync %0, 256;" :: "r"(id) : "memory");
}
// x = hi + lo with hi = rn_fp16(x); x - hi exact in fp32
__device__ __forceinline__ void split_fp16(float v, unsigned short& h, unsigned short& l) {
    __half hh = __float2half_rn(v);
    float fh = __half2float(hh);
    __half ll = __float2half_rn(v - fh);
    h = *reinterpret_cast<unsigned short*>(&hh);
    l = *reinterpret_cast<unsigned short*>(&ll);
}

// ---- fused precompute: split x (fp16 hi/lo), W -> fp16 swizzled, out = bias ------
__global__ void precompute_kernel(const float* __restrict__ x,
                                  const float* __restrict__ w,
                                  const float4* __restrict__ bias4,
                                  float4* __restrict__ out4)
{
    int t = blockIdx.x * blockDim.x + threadIdx.x;

    if (t < NIN * 8) {              // split x: 8 floats per thread
        int row = t >> 3, c8 = t & 7;
        const float4* p = (const float4*)(x + (size_t)row * 64 + c8 * 8);
        float4 a = p[0], b = p[1];
        float v[8] = {a.x, a.y, a.z, a.w, b.x, b.y, b.z, b.w};
        unsigned short hi[8], lo[8];
        #pragma unroll
        for (int j = 0; j < 8; j++) split_fp16(v[j], hi[j], lo[j]);
        *(uint4*)(g_xsplit + (size_t)row * 128 + c8 * 8)      = *(uint4*)hi;
        *(uint4*)(g_xsplit + (size_t)row * 128 + 64 + c8 * 8) = *(uint4*)lo;
    }

    if (t < KK * CIN * COUT) {      // W -> fp16; perm r gives consecutive-cout d-frags
        int k = t / 4096, rem = t - k * 4096;
        int c = rem >> 6, o = rem & 63;
        __half hh = __float2half_rn(w[t]);
        int r = ((o >> 1) & 7) * 8 + 2 * (o >> 4) + (o & 1);
        uint32_t off = (uint32_t)r * 128 + (uint32_t)c * 2;
        uint32_t sw  = off ^ ((off >> 3) & 0x70);
        g_wh[(size_t)k * 4096 + (sw >> 1)] = *reinterpret_cast<unsigned short*>(&hh);
    }

    if (t < NOUT * (COUT / 4)) {    // out = bias broadcast
        out4[t] = bias4[t & (COUT / 4 - 1)];
    }
}

// ---- prefetch 8 rule indices for a tile (this thread's gather slots) -------------
__device__ __forceinline__ void idx_prefetch(int t, int k, const int* __restrict__ in_idx,
                                             int gt, int* idxbuf)
{
    const int gi8 = (gt >> 3) & 31;
    #pragma unroll
    for (int it = 0; it < 8; it++) {
        int hid = it * 32 + gi8;
        int rl  = hid >> 1;
        int rg  = t * TILE + rl;
        idxbuf[it] = (rg < RR) ? __ldg(&in_idx[k * RR + rg]) : -1;
    }
}

// ---- async gather of ONE tile using prefetched indices ---------------------------
__device__ __forceinline__ void gather_tile_buf(uint32_t sbase, int g, int sidx,
                                                const int* idxbuf, int gt)
{
    const int gchunk = gt & 7;
    const int gi8    = (gt >> 3) & 31;
    const uint32_t base = sbase + OFF_A + (uint32_t)g * GRP_B + (uint32_t)sidx * STG_SZ;
    #pragma unroll
    for (int it = 0; it < 8; it++) {
        int hid  = it * 32 + gi8;
        int rl   = hid >> 1;
        int half = hid & 1;
        int gi   = idxbuf[it];
        if (gi >= 0) {
            const void* src = (const char*)(g_xsplit + (size_t)gi * 128 + half * 64)
                            + gchunk * 16;
            uint32_t off = (uint32_t)rl * 128 + gchunk * 16;
            uint32_t sw  = off ^ ((off >> 3) & 0x70);
            uint32_t dst = base + (uint32_t)half * 16384u + sw;
            asm volatile("cp.async.cg.shared.global [%0], [%1], 16;"
                         :: "r"(dst), "l"(src) : "memory");
        }
    }
    asm volatile("cp.async.commit_group;" ::: "memory");
}

// ---- main: 2 pipelines, Bh in regs, idx prefetch, A-frag double buffer -----------
extern "C" __global__ void __launch_bounds__(THREADS, 1)
sparse_mma_kernel(const int* __restrict__ in_idx,
                  const int* __restrict__ out_idx,
                  float*     __restrict__ out)
{
    extern __shared__ __align__(1024) char smem[];
    const uint32_t sbase = smem_u32(smem);
    const int tid  = threadIdx.x;
    const int lane = tid & 31;
    const int wrp  = tid >> 5;          // 0..15
    const int g    = wrp >> 3;          // group 0/1
    const int wg   = wrp & 7;           // warp within group
    const int gt   = tid & 255;         // thread within group
    const int k    = blockIdx.y;
    const int tbase = blockIdx.x * TPB;

    int idxbuf[8];

    // prologue: gathers for first 2 tiles of this group (inline idx), stage W
    idx_prefetch(tbase + g, k, in_idx, gt, idxbuf);
    gather_tile_buf(sbase, g, 0, idxbuf, gt);
    idx_prefetch(tbase + 2 + g, k, in_idx, gt, idxbuf);
    gather_tile_buf(sbase, g, 1, idxbuf, gt);
    // preload indices for tile local-index 2 (issued at loop i=0)
    idx_prefetch(tbase + 4 + g, k, in_idx, gt, idxbuf);
    {
        const uint4* wgp = (const uint4*)(g_wh + (size_t)k * 4096);
        uint4*       wsm = (uint4*)(smem + OFF_WH);
        #pragma unroll
        for (int i = tid; i < 512; i += THREADS) wsm[i] = wgp[i];
    }
    __syncthreads();   // W visible for B-frag ldmatrix

    // warp roles within group: n-half h, rule-slice s8 (32 rules each)
    const int h   = wg & 1;
    const int s8  = wg >> 1;            // 0..3
    const int mrow0 = s8 * 32 + (lane & 15);

    // ---- B fragments (wh only): load ONCE into registers ----
    uint32_t Bh[4][8];
    {
        const uint32_t b_xor  = (uint32_t)((lane & 7) << 4);
        const uint32_t b_kofs = (uint32_t)(((lane >> 3) & 1) * 16);
        uint32_t b_rb[2];
        #pragma unroll
        for (int pp = 0; pp < 2; pp++) {
            int p = 2 * h + pp;
            b_rb[pp] = (uint32_t)(((2 * p + (lane >> 4)) * 8 + (lane & 7)) * 128);
        }
        #pragma unroll
        for (int ks = 0; ks < 4; ks++) {
            uint32_t colb = (uint32_t)(32 * ks) + b_kofs;
            #pragma unroll
            for (int pp = 0; pp < 2; pp++)
                ldm4(sbase + OFF_WH + b_rb[pp] + (colb ^ b_xor),
                     Bh[ks][4 * pp], Bh[ks][4 * pp + 1], Bh[ks][4 * pp + 2], Bh[ks][4 * pp + 3]);
        }
    }

    // A ldmatrix addressing (per mb: +16 rows = +2048B)
    const uint32_t a_xor0 = (uint32_t)((mrow0 & 7) << 4);
    const uint32_t a_rb   = (uint32_t)mrow0 * 128u;
    const uint32_t a_kofs = (uint32_t)(((lane >> 4) & 1) * 16);
    const uint32_t gbase  = sbase + OFF_A + (uint32_t)g * GRP_B;

    // epilogue constants
    const int tq    = lane & 3;
    const int rrow  = 32 * s8 + (lane >> 2);
    const int cbase = 16 * tq + 8 * h;
    const int barid = 1 + g;

    #pragma unroll 1
    for (int i = 0; i < TPG; i++) {
        int t = tbase + 2 * i + g;

        // wait for this tile's gather, group-local visibility barrier
        if (i < TPG - 1) asm volatile("cp.async.wait_group 1;" ::: "memory");
        else             asm volatile("cp.async.wait_group 0;" ::: "memory");
        bar_grp(barid);   // also: group finished reading stage (i-1)%3 last iter

        // issue gather for tile i+2 (indices already in registers)
        if (i + 2 < TPG)
            gather_tile_buf(sbase, g, (i + 2) % 3, idxbuf, gt);

        // prefetch this tile's 4 output indices (hides under MMA below)
        int obuf[4];
        #pragma unroll
        for (int mb = 0; mb < 2; mb++) {
            int rg1 = t * TILE + rrow + 16 * mb;
            int rg2 = rg1 + 8;
            obuf[2 * mb]     = (rg1 < RR) ? __ldg(&out_idx[k * RR + rg1]) : -1;
            obuf[2 * mb + 1] = (rg2 < RR) ? __ldg(&out_idx[k * RR + rg2]) : -1;
        }
        // prefetch rule indices for tile i+3 (used 2 iterations from now)
        if (i + 3 < TPG)
            idx_prefetch(tbase + 2 * (i + 3) + g, k, in_idx, gt, idxbuf);

        // ---- MMA with A-frag double buffer over flat (mb,ks) steps ----
        const uint32_t stage = gbase + (uint32_t)(i % 3) * STG_SZ;
        const uint32_t ab    = stage + a_rb;

        // frag buffers: [0..3]=hi, [4..7]=lo
        uint32_t cur[8], nxt[8];
        {   // load step 0: mb=0, ks=0
            uint32_t cola = a_kofs;
            ldm4(ab + (cola ^ a_xor0), cur[0], cur[1], cur[2], cur[3]);
            ldm4(ab + 16384u + (cola ^ a_xor0), cur[4], cur[5], cur[6], cur[7]);
        }

        #pragma unroll
        for (int mb = 0; mb < 2; mb++) {
            float4 acc[4];
            #pragma unroll
            for (int q = 0; q < 4; q++) acc[q] = make_float4(0.f, 0.f, 0.f, 0.f);

            #pragma unroll
            for (int ks = 0; ks < 4; ks++) {
                // prefetch next step's A frags (next ks, or mb=1 ks=0)
                int step = mb * 4 + ks;
                if (step < 7) {
                    int nmb = (step + 1) >> 2, nks = (step + 1) & 3;
                    uint32_t cola = (uint32_t)(32 * nks) + a_kofs;
                    uint32_t nab  = ab + (uint32_t)nmb * 2048u;
                    ldm4(nab + (cola ^ a_xor0), nxt[0], nxt[1], nxt[2], nxt[3]);
                    ldm4(nab + 16384u + (cola ^ a_xor0), nxt[4], nxt[5], nxt[6], nxt[7]);
                }
                // 8 HMMA on cur: (xh + xl) * wh
                #pragma unroll
                for (int q = 0; q < 4; q++)
                    mma_f16(acc[q], cur[0], cur[1], cur[2], cur[3],
                            Bh[ks][2 * q], Bh[ks][2 * q + 1]);
                #pragma unroll
                for (int q = 0; q < 4; q++)
                    mma_f16(acc[q], cur[4], cur[5], cur[6], cur[7],
                            Bh[ks][2 * q], Bh[ks][2 * q + 1]);
                // rotate buffers
                if (step < 7) {
                    #pragma unroll
                    for (int j = 0; j < 8; j++) cur[j] = nxt[j];
                }
            }

            int o1 = obuf[2 * mb], o2 = obuf[2 * mb + 1];
            if (o1 >= 0) {
                float* b = out + (size_t)o1 * COUT + cbase;
                red4(b,     acc[0].x, acc[0].y, acc[1].x, acc[1].y);
                red4(b + 4, acc[2].x, acc[2].y, acc[3].x, acc[3].y);
            }
            if (o2 >= 0) {
                float* b = out + (size_t)o2 * COUT + cbase;
                red4(b,     acc[0].z, acc[0].w, acc[1].z, acc[1].w);
                red4(b + 4, acc[2].z, acc[2].w, acc[3].z, acc[3].w);
            }
        }
    }
}

extern "C" void kernel_launch(void* const* d_in, const int* in_sizes, int n_in,
                              void* d_out, int out_size)
{
    const float* x       = (const float*)d_in[0];
    const float* w       = (const float*)d_in[1];
    const float* bias    = (const float*)d_in[2];
    const int*   in_idx  = (const int*)d_in[3];
    const int*   out_idx = (const int*)d_in[4];
    float*       out     = (float*)d_out;

    {   // fused: split x, convert W, out = bias
        int nmax = NOUT * (COUT / 4);   // largest range (2.4M)
        precompute_kernel<<<(nmax + 255) / 256, 256>>>(x, w, (const float4*)bias,
                                                       (float4*)out);
    }

    cudaFuncSetAttribute(sparse_mma_kernel,
                         cudaFuncAttributeMaxDynamicSharedMemorySize, SMEM_BYTES);
    dim3 grid(NBX, KK);
    sparse_mma_kernel<<<grid, THREADS, SMEM_BYTES>>>(in_idx, out_idx, out);
}

// round 14
// speedup vs baseline: 1.1705x; 1.1705x over previous
#include <cuda_runtime.h>
#include <cuda_fp16.h>
#include <cstdint>

// Problem constants
#define KK   27
#define RR   50000
#define CIN  64
#define COUT 64
#define NIN  150000
#define NOUT 150000

#define TILE    128
#define NTILES  ((RR + TILE - 1) / TILE)      // 391
#define TPB     14                            // tiles per block
#define TPG     7                             // tiles per group (2 groups)
#define NBX     ((NTILES + TPB - 1) / TPB)    // 28
#define THREADS 512

// SMEM: W(hi) 8K, then per-group 3 stages x 16K (stage = one tile A-hi)
#define OFF_WH  0u
#define OFF_A   8192u
#define STG_SZ  16384u
#define GRP_B   49152u      // 3 * 16384
#define SMEM_BYTES (8192u + 2u * GRP_B)       // 106496

// ---- global scratch ----------------------------------------------------------
__device__ __align__(16) unsigned short g_xh[(size_t)NIN * 64];    // fp16 x
__device__ __align__(16) unsigned short g_wh[(size_t)KK * 4096];   // fp16 wh swizzled

// ---- helpers -------------------------------------------------------------------
__device__ __forceinline__ uint32_t smem_u32(const void* p) {
    uint32_t a;
    asm("{ .reg .u64 t; cvta.to.shared.u64 t, %1; cvt.u32.u64 %0, t; }" : "=r"(a) : "l"(p));
    return a;
}
__device__ __forceinline__ void ldm4(uint32_t addr, uint32_t& r0, uint32_t& r1,
                                     uint32_t& r2, uint32_t& r3) {
    asm volatile("ldmatrix.sync.aligned.m8n8.x4.shared.b16 {%0,%1,%2,%3}, [%4];"
                 : "=r"(r0), "=r"(r1), "=r"(r2), "=r"(r3) : "r"(addr));
}
__device__ __forceinline__ void mma_f16(float4& d,
                                        uint32_t a0, uint32_t a1, uint32_t a2, uint32_t a3,
                                        uint32_t b0, uint32_t b1) {
    asm volatile("mma.sync.aligned.m16n8k16.row.col.f32.f16.f16.f32 "
                 "{%0,%1,%2,%3}, {%4,%5,%6,%7}, {%8,%9}, {%0,%1,%2,%3};"
                 : "+f"(d.x), "+f"(d.y), "+f"(d.z), "+f"(d.w)
                 : "r"(a0), "r"(a1), "r"(a2), "r"(a3), "r"(b0), "r"(b1));
}
__device__ __forceinline__ void red4(float* p, float a, float b, float c, float d) {
    asm volatile("red.global.add.v4.f32 [%0], {%1, %2, %3, %4};"
                 :: "l"(p), "f"(a), "f"(b), "f"(c), "f"(d) : "memory");
}
__device__ __forceinline__ void bar_grp(int id) {
    asm volatile("bar.sync %0, 256;" :: "r"(id) : "memory");
}

// ---- fused precompute: x -> fp16, W -> fp16 swizzled, out = bias -----------------
__global__ void precompute_kernel(const float* __restrict__ x,
                                  const float* __restrict__ w,
                                  const float4* __restrict__ bias4,
                                  float4* __restrict__ out4)
{
    int t = blockIdx.x * blockDim.x + threadIdx.x;

    if (t < NIN * 8) {              // convert x: 8 floats per thread
        int row = t >> 3, c8 = t & 7;
        const float4* p = (const float4*)(x + (size_t)row * 64 + c8 * 8);
        float4 a = p[0], b = p[1];
        float v[8] = {a.x, a.y, a.z, a.w, b.x, b.y, b.z, b.w};
        unsigned short hi[8];
        #pragma unroll
        for (int j = 0; j < 8; j++) {
            __half hh = __float2half_rn(v[j]);
            hi[j] = *reinterpret_cast<unsigned short*>(&hh);
        }
        *(uint4*)(g_xh + (size_t)row * 64 + c8 * 8) = *(uint4*)hi;
    }

    if (t < KK * CIN * COUT) {      // W -> fp16; perm r gives consecutive-cout d-frags
        int k = t / 4096, rem = t - k * 4096;
        int c = rem >> 6, o = rem & 63;
        __half hh = __float2half_rn(w[t]);
        int r = ((o >> 1) & 7) * 8 + 2 * (o >> 4) + (o & 1);
        uint32_t off = (uint32_t)r * 128 + (uint32_t)c * 2;
        uint32_t sw  = off ^ ((off >> 3) & 0x70);
        g_wh[(size_t)k * 4096 + (sw >> 1)] = *reinterpret_cast<unsigned short*>(&hh);
    }

    if (t < NOUT * (COUT / 4)) {    // out = bias broadcast
        out4[t] = bias4[t & (COUT / 4 - 1)];
    }
}

// ---- prefetch 4 rule indices for a tile (this thread's gather slots) -------------
__device__ __forceinline__ void idx_prefetch(int t, int k, const int* __restrict__ in_idx,
                                             int gt, int* idxbuf)
{
    const int gr = gt >> 3;            // row group 0..31
    #pragma unroll
    for (int it = 0; it < 4; it++) {
        int rl = it * 32 + gr;
        int rg = t * TILE + rl;
        idxbuf[it] = (rg < RR) ? __ldg(&in_idx[k * RR + rg]) : -1;
    }
}

// ---- async gather of ONE tile (fp16 rows) using prefetched indices ---------------
__device__ __forceinline__ void gather_tile_buf(uint32_t sbase, int g, int sidx,
                                                const int* idxbuf, int gt)
{
    const int gchunk = gt & 7;         // 16B chunk within 128B row
    const int gr     = gt >> 3;        // row group
    const uint32_t base = sbase + OFF_A + (uint32_t)g * GRP_B + (uint32_t)sidx * STG_SZ;
    #pragma unroll
    for (int it = 0; it < 4; it++) {
        int rl = it * 32 + gr;
        int gi = idxbuf[it];
        if (gi >= 0) {
            const void* src = (const char*)(g_xh + (size_t)gi * 64) + gchunk * 16;
            uint32_t off = (uint32_t)rl * 128 + gchunk * 16;
            uint32_t sw  = off ^ ((off >> 3) & 0x70);
            asm volatile("cp.async.cg.shared.global [%0], [%1], 16;"
                         :: "r"(base + sw), "l"(src) : "memory");
        }
    }
    asm volatile("cp.async.commit_group;" ::: "memory");
}

// ---- main: 2 pipelines, Bh in regs, idx prefetch, A-frag double buffer -----------
extern "C" __global__ void __launch_bounds__(THREADS, 1)
sparse_mma_kernel(const int* __restrict__ in_idx,
                  const int* __restrict__ out_idx,
                  float*     __restrict__ out)
{
    extern __shared__ __align__(1024) char smem[];
    const uint32_t sbase = smem_u32(smem);
    const int tid  = threadIdx.x;
    const int lane = tid & 31;
    const int wrp  = tid >> 5;          // 0..15
    const int g    = wrp >> 3;          // group 0/1
    const int wg   = wrp & 7;           // warp within group
    const int gt   = tid & 255;         // thread within group
    const int k    = blockIdx.y;
    const int tbase = blockIdx.x * TPB;

    int idxbuf[4];

    // prologue: gathers for first 2 tiles of this group, stage W
    idx_prefetch(tbase + g, k, in_idx, gt, idxbuf);
    gather_tile_buf(sbase, g, 0, idxbuf, gt);
    idx_prefetch(tbase + 2 + g, k, in_idx, gt, idxbuf);
    gather_tile_buf(sbase, g, 1, idxbuf, gt);
    // preload indices for tile local-index 2 (issued at loop i=0)
    idx_prefetch(tbase + 4 + g, k, in_idx, gt, idxbuf);
    {
        const uint4* wgp = (const uint4*)(g_wh + (size_t)k * 4096);
        uint4*       wsm = (uint4*)(smem + OFF_WH);
        #pragma unroll
        for (int i = tid; i < 512; i += THREADS) wsm[i] = wgp[i];
    }
    __syncthreads();   // W visible for B-frag ldmatrix

    // warp roles within group: n-half h, rule-slice s8 (32 rules each)
    const int h   = wg & 1;
    const int s8  = wg >> 1;            // 0..3
    const int mrow0 = s8 * 32 + (lane & 15);

    // ---- B fragments (wh): load ONCE into registers ----
    uint32_t Bh[4][8];
    {
        const uint32_t b_xor  = (uint32_t)((lane & 7) << 4);
        const uint32_t b_kofs = (uint32_t)(((lane >> 3) & 1) * 16);
        uint32_t b_rb[2];
        #pragma unroll
        for (int pp = 0; pp < 2; pp++) {
            int p = 2 * h + pp;
            b_rb[pp] = (uint32_t)(((2 * p + (lane >> 4)) * 8 + (lane & 7)) * 128);
        }
        #pragma unroll
        for (int ks = 0; ks < 4; ks++) {
            uint32_t colb = (uint32_t)(32 * ks) + b_kofs;
            #pragma unroll
            for (int pp = 0; pp < 2; pp++)
                ldm4(sbase + OFF_WH + b_rb[pp] + (colb ^ b_xor),
                     Bh[ks][4 * pp], Bh[ks][4 * pp + 1], Bh[ks][4 * pp + 2], Bh[ks][4 * pp + 3]);
        }
    }

    // A ldmatrix addressing (per mb: +16 rows = +2048B)
    const uint32_t a_xor0 = (uint32_t)((mrow0 & 7) << 4);
    const uint32_t a_rb   = (uint32_t)mrow0 * 128u;
    const uint32_t a_kofs = (uint32_t)(((lane >> 4) & 1) * 16);
    const uint32_t gbase  = sbase + OFF_A + (uint32_t)g * GRP_B;

    // epilogue constants
    const int tq    = lane & 3;
    const int rrow  = 32 * s8 + (lane >> 2);
    const int cbase = 16 * tq + 8 * h;
    const int barid = 1 + g;

    #pragma unroll 1
    for (int i = 0; i < TPG; i++) {
        int t = tbase + 2 * i + g;

        // wait for this tile's gather, group-local visibility barrier
        if (i < TPG - 1) asm volatile("cp.async.wait_group 1;" ::: "memory");
        else             asm volatile("cp.async.wait_group 0;" ::: "memory");
        bar_grp(barid);   // also: group finished reading stage (i-1)%3 last iter

        // issue gather for tile i+2 (indices already in registers)
        if (i + 2 < TPG)
            gather_tile_buf(sbase, g, (i + 2) % 3, idxbuf, gt);

        // prefetch this tile's 4 output indices (hides under MMA below)
        int obuf[4];
        #pragma unroll
        for (int mb = 0; mb < 2; mb++) {
            int rg1 = t * TILE + rrow + 16 * mb;
            int rg2 = rg1 + 8;
            obuf[2 * mb]     = (rg1 < RR) ? __ldg(&out_idx[k * RR + rg1]) : -1;
            obuf[2 * mb + 1] = (rg2 < RR) ? __ldg(&out_idx[k * RR + rg2]) : -1;
        }
        // prefetch rule indices for tile i+3 (used 2 iterations from now)
        if (i + 3 < TPG)
            idx_prefetch(tbase + 2 * (i + 3) + g, k, in_idx, gt, idxbuf);

        // ---- MMA with A-frag double buffer over flat (mb,ks) steps ----
        const uint32_t stage = gbase + (uint32_t)(i % 3) * STG_SZ;
        const uint32_t ab    = stage + a_rb;

        uint32_t cur[4], nxt[4];
        {   // load step 0: mb=0, ks=0
            uint32_t cola = a_kofs;
            ldm4(ab + (cola ^ a_xor0), cur[0], cur[1], cur[2], cur[3]);
        }

        #pragma unroll
        for (int mb = 0; mb < 2; mb++) {
            float4 acc[4];
            #pragma unroll
            for (int q = 0; q < 4; q++) acc[q] = make_float4(0.f, 0.f, 0.f, 0.f);

            #pragma unroll
            for (int ks = 0; ks < 4; ks++) {
                // prefetch next step's A frags (next ks, or mb=1 ks=0)
                int step = mb * 4 + ks;
                if (step < 7) {
                    int nmb = (step + 1) >> 2, nks = (step + 1) & 3;
                    uint32_t cola = (uint32_t)(32 * nks) + a_kofs;
                    uint32_t nab  = ab + (uint32_t)nmb * 2048u;
                    ldm4(nab + (cola ^ a_xor0), nxt[0], nxt[1], nxt[2], nxt[3]);
                }
                // 4 HMMA on cur
                #pragma unroll
                for (int q = 0; q < 4; q++)
                    mma_f16(acc[q], cur[0], cur[1], cur[2], cur[3],
                            Bh[ks][2 * q], Bh[ks][2 * q + 1]);
                // rotate
                if (step < 7) {
                    #pragma unroll
                    for (int j = 0; j < 4; j++) cur[j] = nxt[j];
                }
            }

            int o1 = obuf[2 * mb], o2 = obuf[2 * mb + 1];
            if (o1 >= 0) {
                float* b = out + (size_t)o1 * COUT + cbase;
                red4(b,     acc[0].x, acc[0].y, acc[1].x, acc[1].y);
                red4(b + 4, acc[2].x, acc[2].y, acc[3].x, acc[3].y);
            }
            if (o2 >= 0) {
                float* b = out + (size_t)o2 * COUT + cbase;
                red4(b,     acc[0].z, acc[0].w, acc[1].z, acc[1].w);
                red4(b + 4, acc[2].z, acc[2].w, acc[3].z, acc[3].w);
            }
        }
    }
}

extern "C" void kernel_launch(void* const* d_in, const int* in_sizes, int n_in,
                              void* d_out, int out_size)
{
    const float* x       = (const float*)d_in[0];
    const float* w       = (const float*)d_in[1];
    const float* bias    = (const float*)d_in[2];
    const int*   in_idx  = (const int*)d_in[3];
    const int*   out_idx = (const int*)d_in[4];
    float*       out     = (float*)d_out;

    {   // fused: convert x, convert W, out = bias
        int nmax = NOUT * (COUT / 4);   // largest range (2.4M)
        precompute_kernel<<<(nmax + 255) / 256, 256>>>(x, w, (const float4*)bias,
                                                       (float4*)out);
    }

    cudaFuncSetAttribute(sparse_mma_kernel,
                         cudaFuncAttributeMaxDynamicSharedMemorySize, SMEM_BYTES);
    dim3 grid(NBX, KK);
    sparse_mma_kernel<<<grid, THREADS, SMEM_BYTES>>>(in_idx, out_idx, out);
}

// round 15
// speedup vs baseline: 1.2447x; 1.0634x over previous
#include <cuda_runtime.h>
#include <cuda_fp16.h>
#include <cstdint>

// Problem constants
#define KK   27
#define RR   50000
#define CIN  64
#define COUT 64
#define NIN  150000
#define NOUT 150000

#define TILE    128
#define NTILES  ((RR + TILE - 1) / TILE)      // 391
#define TPG     7                             // tiles per block
#define NBX     ((NTILES + TPG - 1) / TPG)    // 56
#define THREADS 256

// SMEM: W(hi) 8K, then 3 stages x 16K (stage = one tile A)
#define OFF_WH  0u
#define OFF_A   8192u
#define STG_SZ  16384u
#define SMEM_BYTES (8192u + 3u * STG_SZ)      // 57344

// ---- global scratch ----------------------------------------------------------
__device__ __align__(16) unsigned short g_xh[(size_t)NIN * 64];    // fp16 x
__device__ __align__(16) unsigned short g_wh[(size_t)KK * 4096];   // fp16 wh swizzled

// ---- helpers -------------------------------------------------------------------
__device__ __forceinline__ uint32_t smem_u32(const void* p) {
    uint32_t a;
    asm("{ .reg .u64 t; cvta.to.shared.u64 t, %1; cvt.u32.u64 %0, t; }" : "=r"(a) : "l"(p));
    return a;
}
__device__ __forceinline__ void ldm4(uint32_t addr, uint32_t& r0, uint32_t& r1,
                                     uint32_t& r2, uint32_t& r3) {
    asm volatile("ldmatrix.sync.aligned.m8n8.x4.shared.b16 {%0,%1,%2,%3}, [%4];"
                 : "=r"(r0), "=r"(r1), "=r"(r2), "=r"(r3) : "r"(addr));
}
__device__ __forceinline__ void mma_f16(float4& d,
                                        uint32_t a0, uint32_t a1, uint32_t a2, uint32_t a3,
                                        uint32_t b0, uint32_t b1) {
    asm volatile("mma.sync.aligned.m16n8k16.row.col.f32.f16.f16.f32 "
                 "{%0,%1,%2,%3}, {%4,%5,%6,%7}, {%8,%9}, {%0,%1,%2,%3};"
                 : "+f"(d.x), "+f"(d.y), "+f"(d.z), "+f"(d.w)
                 : "r"(a0), "r"(a1), "r"(a2), "r"(a3), "r"(b0), "r"(b1));
}
__device__ __forceinline__ void red4(float* p, float a, float b, float c, float d) {
    asm volatile("red.global.add.v4.f32 [%0], {%1, %2, %3, %4};"
                 :: "l"(p), "f"(a), "f"(b), "f"(c), "f"(d) : "memory");
}

// ---- fused precompute: x -> fp16, W -> fp16 swizzled, out = bias -----------------
__global__ void precompute_kernel(const float* __restrict__ x,
                                  const float* __restrict__ w,
                                  const float4* __restrict__ bias4,
                                  float4* __restrict__ out4)
{
    int t = blockIdx.x * blockDim.x + threadIdx.x;

    if (t < NIN * 8) {              // convert x: 8 floats per thread
        int row = t >> 3, c8 = t & 7;
        const float4* p = (const float4*)(x + (size_t)row * 64 + c8 * 8);
        float4 a = p[0], b = p[1];
        float v[8] = {a.x, a.y, a.z, a.w, b.x, b.y, b.z, b.w};
        unsigned short hi[8];
        #pragma unroll
        for (int j = 0; j < 8; j++) {
            __half hh = __float2half_rn(v[j]);
            hi[j] = *reinterpret_cast<unsigned short*>(&hh);
        }
        *(uint4*)(g_xh + (size_t)row * 64 + c8 * 8) = *(uint4*)hi;
    }

    if (t < KK * CIN * COUT) {      // W -> fp16; perm r gives consecutive-cout d-frags
        int k = t / 4096, rem = t - k * 4096;
        int c = rem >> 6, o = rem & 63;
        __half hh = __float2half_rn(w[t]);
        int r = ((o >> 1) & 7) * 8 + 2 * (o >> 4) + (o & 1);
        uint32_t off = (uint32_t)r * 128 + (uint32_t)c * 2;
        uint32_t sw  = off ^ ((off >> 3) & 0x70);
        g_wh[(size_t)k * 4096 + (sw >> 1)] = *reinterpret_cast<unsigned short*>(&hh);
    }

    if (t < NOUT * (COUT / 4)) {    // out = bias broadcast
        out4[t] = bias4[t & (COUT / 4 - 1)];
    }
}

// ---- prefetch 4 rule indices for a tile (this thread's gather slots) -------------
__device__ __forceinline__ void idx_prefetch(int t, int k, const int* __restrict__ in_idx,
                                             int tid, int* idxbuf)
{
    const int gr = tid >> 3;           // row group 0..31
    #pragma unroll
    for (int it = 0; it < 4; it++) {
        int rl = it * 32 + gr;
        int rg = t * TILE + rl;
        idxbuf[it] = (rg < RR) ? __ldg(&in_idx[k * RR + rg]) : -1;
    }
}

// ---- async gather of ONE tile (fp16 rows) using prefetched indices ---------------
__device__ __forceinline__ void gather_tile_buf(uint32_t sbase, int sidx,
                                                const int* idxbuf, int tid)
{
    const int gchunk = tid & 7;        // 16B chunk within 128B row
    const int gr     = tid >> 3;       // row group
    const uint32_t base = sbase + OFF_A + (uint32_t)sidx * STG_SZ;
    #pragma unroll
    for (int it = 0; it < 4; it++) {
        int rl = it * 32 + gr;
        int gi = idxbuf[it];
        if (gi >= 0) {
            const void* src = (const char*)(g_xh + (size_t)gi * 64) + gchunk * 16;
            uint32_t off = (uint32_t)rl * 128 + gchunk * 16;
            uint32_t sw  = off ^ ((off >> 3) & 0x70);
            asm volatile("cp.async.cg.shared.global [%0], [%1], 16;"
                         :: "r"(base + sw), "l"(src) : "memory");
        }
    }
    asm volatile("cp.async.commit_group;" ::: "memory");
}

// ---- main: 256-thr block = one pipeline; 3 blocks/SM; Bh in regs -----------------
extern "C" __global__ void __launch_bounds__(THREADS, 3)
sparse_mma_kernel(const int* __restrict__ in_idx,
                  const int* __restrict__ out_idx,
                  float*     __restrict__ out)
{
    extern __shared__ __align__(1024) char smem[];
    const uint32_t sbase = smem_u32(smem);
    const int tid  = threadIdx.x;
    const int lane = tid & 31;
    const int wrp  = tid >> 5;          // 0..7
    const int k    = blockIdx.y;
    const int tbase = blockIdx.x * TPG;

    int idxbuf[4];

    // prologue: gathers for first 2 tiles, stage W
    idx_prefetch(tbase, k, in_idx, tid, idxbuf);
    gather_tile_buf(sbase, 0, idxbuf, tid);
    idx_prefetch(tbase + 1, k, in_idx, tid, idxbuf);
    gather_tile_buf(sbase, 1, idxbuf, tid);
    // preload indices for tile 2 (issued at loop i=0)
    idx_prefetch(tbase + 2, k, in_idx, tid, idxbuf);
    {
        const uint4* wgp = (const uint4*)(g_wh + (size_t)k * 4096);
        uint4*       wsm = (uint4*)(smem + OFF_WH);
        #pragma unroll
        for (int i = tid; i < 512; i += THREADS) wsm[i] = wgp[i];
    }
    __syncthreads();   // W visible for B-frag ldmatrix

    // warp roles: n-half h, rule-slice s8 (32 rules each)
    const int h   = wrp & 1;
    const int s8  = wrp >> 1;           // 0..3
    const int mrow0 = s8 * 32 + (lane & 15);

    // ---- B fragments (wh): load ONCE into registers ----
    uint32_t Bh[4][8];
    {
        const uint32_t b_xor  = (uint32_t)((lane & 7) << 4);
        const uint32_t b_kofs = (uint32_t)(((lane >> 3) & 1) * 16);
        uint32_t b_rb[2];
        #pragma unroll
        for (int pp = 0; pp < 2; pp++) {
            int p = 2 * h + pp;
            b_rb[pp] = (uint32_t)(((2 * p + (lane >> 4)) * 8 + (lane & 7)) * 128);
        }
        #pragma unroll
        for (int ks = 0; ks < 4; ks++) {
            uint32_t colb = (uint32_t)(32 * ks) + b_kofs;
            #pragma unroll
            for (int pp = 0; pp < 2; pp++)
                ldm4(sbase + OFF_WH + b_rb[pp] + (colb ^ b_xor),
                     Bh[ks][4 * pp], Bh[ks][4 * pp + 1], Bh[ks][4 * pp + 2], Bh[ks][4 * pp + 3]);
        }
    }

    // A ldmatrix addressing (per mb: +16 rows = +2048B)
    const uint32_t a_xor0 = (uint32_t)((mrow0 & 7) << 4);
    const uint32_t a_rb   = (uint32_t)mrow0 * 128u;
    const uint32_t a_kofs = (uint32_t)(((lane >> 4) & 1) * 16);

    // epilogue constants
    const int tq    = lane & 3;
    const int rrow  = 32 * s8 + (lane >> 2);
    const int cbase = 16 * tq + 8 * h;

    #pragma unroll 1
    for (int i = 0; i < TPG; i++) {
        int t = tbase + i;

        // wait for this tile's gather, block-wide visibility barrier
        if (i < TPG - 1) asm volatile("cp.async.wait_group 1;" ::: "memory");
        else             asm volatile("cp.async.wait_group 0;" ::: "memory");
        __syncthreads();   // also: block finished reading stage (i-1)%3 last iter

        // issue gather for tile i+2 (indices already in registers)
        if (i + 2 < TPG)
            gather_tile_buf(sbase, (i + 2) % 3, idxbuf, tid);

        // prefetch this tile's 4 output indices (hides under MMA below)
        int obuf[4];
        #pragma unroll
        for (int mb = 0; mb < 2; mb++) {
            int rg1 = t * TILE + rrow + 16 * mb;
            int rg2 = rg1 + 8;
            obuf[2 * mb]     = (rg1 < RR) ? __ldg(&out_idx[k * RR + rg1]) : -1;
            obuf[2 * mb + 1] = (rg2 < RR) ? __ldg(&out_idx[k * RR + rg2]) : -1;
        }
        // prefetch rule indices for tile i+3 (used 2 iterations from now)
        if (i + 3 < TPG)
            idx_prefetch(tbase + i + 3, k, in_idx, tid, idxbuf);

        // ---- MMA with A-frag double buffer over flat (mb,ks) steps ----
        const uint32_t ab = sbase + OFF_A + (uint32_t)(i % 3) * STG_SZ + a_rb;

        uint32_t cur[4], nxt[4];
        {   // load step 0: mb=0, ks=0
            uint32_t cola = a_kofs;
            ldm4(ab + (cola ^ a_xor0), cur[0], cur[1], cur[2], cur[3]);
        }

        #pragma unroll
        for (int mb = 0; mb < 2; mb++) {
            float4 acc[4];
            #pragma unroll
            for (int q = 0; q < 4; q++) acc[q] = make_float4(0.f, 0.f, 0.f, 0.f);

            #pragma unroll
            for (int ks = 0; ks < 4; ks++) {
                // prefetch next step's A frags (next ks, or mb=1 ks=0)
                int step = mb * 4 + ks;
                if (step < 7) {
                    int nmb = (step + 1) >> 2, nks = (step + 1) & 3;
                    uint32_t cola = (uint32_t)(32 * nks) + a_kofs;
                    uint32_t nab  = ab + (uint32_t)nmb * 2048u;
                    ldm4(nab + (cola ^ a_xor0), nxt[0], nxt[1], nxt[2], nxt[3]);
                }
                // 4 HMMA on cur
                #pragma unroll
                for (int q = 0; q < 4; q++)
                    mma_f16(acc[q], cur[0], cur[1], cur[2], cur[3],
                            Bh[ks][2 * q], Bh[ks][2 * q + 1]);
                // rotate
                if (step < 7) {
                    #pragma unroll
                    for (int j = 0; j < 4; j++) cur[j] = nxt[j];
                }
            }

            int o1 = obuf[2 * mb], o2 = obuf[2 * mb + 1];
            if (o1 >= 0) {
                float* b = out + (size_t)o1 * COUT + cbase;
                red4(b,     acc[0].x, acc[0].y, acc[1].x, acc[1].y);
                red4(b + 4, acc[2].x, acc[2].y, acc[3].x, acc[3].y);
            }
            if (o2 >= 0) {
                float* b = out + (size_t)o2 * COUT + cbase;
                red4(b,     acc[0].z, acc[0].w, acc[1].z, acc[1].w);
                red4(b + 4, acc[2].z, acc[2].w, acc[3].z, acc[3].w);
            }
        }
    }
}

extern "C" void kernel_launch(void* const* d_in, const int* in_sizes, int n_in,
                              void* d_out, int out_size)
{
    const float* x       = (const float*)d_in[0];
    const float* w       = (const float*)d_in[1];
    const float* bias    = (const float*)d_in[2];
    const int*   in_idx  = (const int*)d_in[3];
    const int*   out_idx = (const int*)d_in[4];
    float*       out     = (float*)d_out;

    {   // fused: convert x, convert W, out = bias
        int nmax = NOUT * (COUT / 4);   // largest range (2.4M)
        precompute_kernel<<<(nmax + 255) / 256, 256>>>(x, w, (const float4*)bias,
                                                       (float4*)out);
    }

    cudaFuncSetAttribute(sparse_mma_kernel,
                         cudaFuncAttributeMaxDynamicSharedMemorySize, SMEM_BYTES);
    dim3 grid(NBX, KK);
    sparse_mma_kernel<<<grid, THREADS, SMEM_BYTES>>>(in_idx, out_idx, out);
}

// round 16
// speedup vs baseline: 1.3723x; 1.1025x over previous
#include <cuda_runtime.h>
#include <cuda_fp16.h>
#include <cstdint>

// Problem constants
#define KK   27
#define RR   50000
#define CIN  64
#define COUT 64
#define NIN  150000
#define NOUT 150000

#define TILE    128
#define NTILES  ((RR + TILE - 1) / TILE)      // 391
#define TPG     8                             // tiles per block
#define NBX     ((NTILES + TPG - 1) / TPG)    // 49
#define THREADS 256

// SMEM: W(hi) 8K, then 3 stages x 16K (stage = one tile A)
#define OFF_WH  0u
#define OFF_A   8192u
#define STG_SZ  16384u
#define SMEM_BYTES (8192u + 3u * STG_SZ)      // 57344

// ---- global scratch ----------------------------------------------------------
__device__ __align__(16) unsigned short g_xh[(size_t)NIN * 64];    // fp16 x
__device__ __align__(16) unsigned short g_wh[(size_t)KK * 4096];   // fp16 wh swizzled

// ---- helpers -------------------------------------------------------------------
__device__ __forceinline__ uint32_t smem_u32(const void* p) {
    uint32_t a;
    asm("{ .reg .u64 t; cvta.to.shared.u64 t, %1; cvt.u32.u64 %0, t; }" : "=r"(a) : "l"(p));
    return a;
}
__device__ __forceinline__ void ldm4(uint32_t addr, uint32_t& r0, uint32_t& r1,
                                     uint32_t& r2, uint32_t& r3) {
    asm volatile("ldmatrix.sync.aligned.m8n8.x4.shared.b16 {%0,%1,%2,%3}, [%4];"
                 : "=r"(r0), "=r"(r1), "=r"(r2), "=r"(r3) : "r"(addr));
}
__device__ __forceinline__ void mma_f16(float4& d,
                                        uint32_t a0, uint32_t a1, uint32_t a2, uint32_t a3,
                                        uint32_t b0, uint32_t b1) {
    asm volatile("mma.sync.aligned.m16n8k16.row.col.f32.f16.f16.f32 "
                 "{%0,%1,%2,%3}, {%4,%5,%6,%7}, {%8,%9}, {%0,%1,%2,%3};"
                 : "+f"(d.x), "+f"(d.y), "+f"(d.z), "+f"(d.w)
                 : "r"(a0), "r"(a1), "r"(a2), "r"(a3), "r"(b0), "r"(b1));
}
__device__ __forceinline__ void red4(float* p, float a, float b, float c, float d) {
    asm volatile("red.global.add.v4.f32 [%0], {%1, %2, %3, %4};"
                 :: "l"(p), "f"(a), "f"(b), "f"(c), "f"(d) : "memory");
}

// ---- fused precompute: x -> fp16, W -> fp16 swizzled, out = bias -----------------
__global__ void precompute_kernel(const float* __restrict__ x,
                                  const float* __restrict__ w,
                                  const float4* __restrict__ bias4,
                                  float4* __restrict__ out4)
{
    int t = blockIdx.x * blockDim.x + threadIdx.x;

    if (t < NIN * 8) {              // convert x: 8 floats per thread
        int row = t >> 3, c8 = t & 7;
        const float4* p = (const float4*)(x + (size_t)row * 64 + c8 * 8);
        float4 a = p[0], b = p[1];
        float v[8] = {a.x, a.y, a.z, a.w, b.x, b.y, b.z, b.w};
        unsigned short hi[8];
        #pragma unroll
        for (int j = 0; j < 8; j++) {
            __half hh = __float2half_rn(v[j]);
            hi[j] = *reinterpret_cast<unsigned short*>(&hh);
        }
        *(uint4*)(g_xh + (size_t)row * 64 + c8 * 8) = *(uint4*)hi;
    }

    if (t < KK * CIN * COUT) {      // W -> fp16; perm gives CONTIGUOUS-cout d-frags:
        // lane (tq,h) covers couts [32h+8tq, +8) -> 128B-coalesced red4 scatter
        int k = t / 4096, rem = t - k * 4096;
        int c = rem >> 6, o = rem & 63;
        __half hh = __float2half_rn(w[t]);
        int r = 32 * ((o >> 5) & 1) + 8 * ((o >> 1) & 3)
              + 2 * ((o >> 3) & 3) + (o & 1);
        uint32_t off = (uint32_t)r * 128 + (uint32_t)c * 2;
        uint32_t sw  = off ^ ((off >> 3) & 0x70);
        g_wh[(size_t)k * 4096 + (sw >> 1)] = *reinterpret_cast<unsigned short*>(&hh);
    }

    if (t < NOUT * (COUT / 4)) {    // out = bias broadcast
        out4[t] = bias4[t & (COUT / 4 - 1)];
    }
}

// ---- prefetch 4 rule indices for a tile (this thread's gather slots) -------------
__device__ __forceinline__ void idx_prefetch(int t, int k, const int* __restrict__ in_idx,
                                             int tid, int* idxbuf)
{
    const int gr = tid >> 3;           // row group 0..31
    #pragma unroll
    for (int it = 0; it < 4; it++) {
        int rl = it * 32 + gr;
        int rg = t * TILE + rl;
        idxbuf[it] = (rg < RR) ? __ldg(&in_idx[k * RR + rg]) : -1;
    }
}

// ---- async gather of ONE tile (fp16 rows) using prefetched indices ---------------
__device__ __forceinline__ void gather_tile_buf(uint32_t sbase, int sidx,
                                                const int* idxbuf, int tid)
{
    const int gchunk = tid & 7;        // 16B chunk within 128B row
    const int gr     = tid >> 3;       // row group
    const uint32_t base = sbase + OFF_A + (uint32_t)sidx * STG_SZ;
    #pragma unroll
    for (int it = 0; it < 4; it++) {
        int rl = it * 32 + gr;
        int gi = idxbuf[it];
        if (gi >= 0) {
            const void* src = (const char*)(g_xh + (size_t)gi * 64) + gchunk * 16;
            uint32_t off = (uint32_t)rl * 128 + gchunk * 16;
            uint32_t sw  = off ^ ((off >> 3) & 0x70);
            asm volatile("cp.async.cg.shared.global [%0], [%1], 16;"
                         :: "r"(base + sw), "l"(src) : "memory");
        }
    }
    asm volatile("cp.async.commit_group;" ::: "memory");
}

// ---- main: 256-thr block = one pipeline; 3 blocks/SM; Bh in regs -----------------
extern "C" __global__ void __launch_bounds__(THREADS, 3)
sparse_mma_kernel(const int* __restrict__ in_idx,
                  const int* __restrict__ out_idx,
                  float*     __restrict__ out)
{
    extern __shared__ __align__(1024) char smem[];
    const uint32_t sbase = smem_u32(smem);
    const int tid  = threadIdx.x;
    const int lane = tid & 31;
    const int wrp  = tid >> 5;          // 0..7
    const int k    = blockIdx.y;
    const int tbase = blockIdx.x * TPG;

    int idxbuf[4];

    // prologue: gathers for first 2 tiles, stage W
    idx_prefetch(tbase, k, in_idx, tid, idxbuf);
    gather_tile_buf(sbase, 0, idxbuf, tid);
    idx_prefetch(tbase + 1, k, in_idx, tid, idxbuf);
    gather_tile_buf(sbase, 1, idxbuf, tid);
    // preload indices for tile 2 (issued at loop i=0)
    idx_prefetch(tbase + 2, k, in_idx, tid, idxbuf);
    {
        const uint4* wgp = (const uint4*)(g_wh + (size_t)k * 4096);
        uint4*       wsm = (uint4*)(smem + OFF_WH);
        #pragma unroll
        for (int i = tid; i < 512; i += THREADS) wsm[i] = wgp[i];
    }
    __syncthreads();   // W visible for B-frag ldmatrix

    // warp roles: n-half h, rule-slice s8 (32 rules each)
    const int h   = wrp & 1;
    const int s8  = wrp >> 1;           // 0..3
    const int mrow0 = s8 * 32 + (lane & 15);

    // ---- B fragments (wh): load ONCE into registers ----
    uint32_t Bh[4][8];
    {
        const uint32_t b_xor  = (uint32_t)((lane & 7) << 4);
        const uint32_t b_kofs = (uint32_t)(((lane >> 3) & 1) * 16);
        uint32_t b_rb[2];
        #pragma unroll
        for (int pp = 0; pp < 2; pp++) {
            int p = 2 * h + pp;
            b_rb[pp] = (uint32_t)(((2 * p + (lane >> 4)) * 8 + (lane & 7)) * 128);
        }
        #pragma unroll
        for (int ks = 0; ks < 4; ks++) {
            uint32_t colb = (uint32_t)(32 * ks) + b_kofs;
            #pragma unroll
            for (int pp = 0; pp < 2; pp++)
                ldm4(sbase + OFF_WH + b_rb[pp] + (colb ^ b_xor),
                     Bh[ks][4 * pp], Bh[ks][4 * pp + 1], Bh[ks][4 * pp + 2], Bh[ks][4 * pp + 3]);
        }
    }

    // A ldmatrix addressing (per mb: +16 rows = +2048B)
    const uint32_t a_xor0 = (uint32_t)((mrow0 & 7) << 4);
    const uint32_t a_rb   = (uint32_t)mrow0 * 128u;
    const uint32_t a_kofs = (uint32_t)(((lane >> 4) & 1) * 16);

    // epilogue constants: lane covers couts [32h+8tq, +8) -> contiguous 32B
    const int tq    = lane & 3;
    const int rrow  = 32 * s8 + (lane >> 2);
    const int cbase = 8 * tq + 32 * h;

    #pragma unroll 1
    for (int i = 0; i < TPG; i++) {
        int t = tbase + i;

        // wait for this tile's gather, block-wide visibility barrier
        if (i < TPG - 1) asm volatile("cp.async.wait_group 1;" ::: "memory");
        else             asm volatile("cp.async.wait_group 0;" ::: "memory");
        __syncthreads();   // also: block finished reading stage (i-1)%3 last iter

        // issue gather for tile i+2 (indices already in registers)
        if (i + 2 < TPG)
            gather_tile_buf(sbase, (i + 2) % 3, idxbuf, tid);

        // prefetch this tile's 4 output indices (hides under MMA below)
        int obuf[4];
        #pragma unroll
        for (int mb = 0; mb < 2; mb++) {
            int rg1 = t * TILE + rrow + 16 * mb;
            int rg2 = rg1 + 8;
            obuf[2 * mb]     = (rg1 < RR) ? __ldg(&out_idx[k * RR + rg1]) : -1;
            obuf[2 * mb + 1] = (rg2 < RR) ? __ldg(&out_idx[k * RR + rg2]) : -1;
        }
        // prefetch rule indices for tile i+3 (used 2 iterations from now)
        if (i + 3 < TPG)
            idx_prefetch(tbase + i + 3, k, in_idx, tid, idxbuf);

        // ---- MMA with A-frag double buffer over flat (mb,ks) steps ----
        const uint32_t ab = sbase + OFF_A + (uint32_t)(i % 3) * STG_SZ + a_rb;

        uint32_t cur[4], nxt[4];
        {   // load step 0: mb=0, ks=0
            uint32_t cola = a_kofs;
            ldm4(ab + (cola ^ a_xor0), cur[0], cur[1], cur[2], cur[3]);
        }

        #pragma unroll
        for (int mb = 0; mb < 2; mb++) {
            float4 acc[4];
            #pragma unroll
            for (int q = 0; q < 4; q++) acc[q] = make_float4(0.f, 0.f, 0.f, 0.f);

            #pragma unroll
            for (int ks = 0; ks < 4; ks++) {
                // prefetch next step's A frags (next ks, or mb=1 ks=0)
                int step = mb * 4 + ks;
                if (step < 7) {
                    int nmb = (step + 1) >> 2, nks = (step + 1) & 3;
                    uint32_t cola = (uint32_t)(32 * nks) + a_kofs;
                    uint32_t nab  = ab + (uint32_t)nmb * 2048u;
                    ldm4(nab + (cola ^ a_xor0), nxt[0], nxt[1], nxt[2], nxt[3]);
                }
                // 4 HMMA on cur
                #pragma unroll
                for (int q = 0; q < 4; q++)
                    mma_f16(acc[q], cur[0], cur[1], cur[2], cur[3],
                            Bh[ks][2 * q], Bh[ks][2 * q + 1]);
                // rotate
                if (step < 7) {
                    #pragma unroll
                    for (int j = 0; j < 4; j++) cur[j] = nxt[j];
                }
            }

            int o1 = obuf[2 * mb], o2 = obuf[2 * mb + 1];
            if (o1 >= 0) {
                float* b = out + (size_t)o1 * COUT + cbase;
                red4(b,     acc[0].x, acc[0].y, acc[1].x, acc[1].y);
                red4(b + 4, acc[2].x, acc[2].y, acc[3].x, acc[3].y);
            }
            if (o2 >= 0) {
                float* b = out + (size_t)o2 * COUT + cbase;
                red4(b,     acc[0].z, acc[0].w, acc[1].z, acc[1].w);
                red4(b + 4, acc[2].z, acc[2].w, acc[3].z, acc[3].w);
            }
        }
    }
}

extern "C" void kernel_launch(void* const* d_in, const int* in_sizes, int n_in,
                              void* d_out, int out_size)
{
    const float* x       = (const float*)d_in[0];
    const float* w       = (const float*)d_in[1];
    const float* bias    = (const float*)d_in[2];
    const int*   in_idx  = (const int*)d_in[3];
    const int*   out_idx = (const int*)d_in[4];
    float*       out     = (float*)d_out;

    {   // fused: convert x, convert W, out = bias
        int nmax = NOUT * (COUT / 4);   // largest range (2.4M)
        precompute_kernel<<<(nmax + 255) / 256, 256>>>(x, w, (const float4*)bias,
                                                       (float4*)out);
    }

    cudaFuncSetAttribute(sparse_mma_kernel,
                         cudaFuncAttributeMaxDynamicSharedMemorySize, SMEM_BYTES);
    dim3 grid(NBX, KK);
    sparse_mma_kernel<<<grid, THREADS, SMEM_BYTES>>>(in_idx, out_idx, out);
}

// round 17
// speedup vs baseline: 1.6519x; 1.2038x over previous
#include <cuda_runtime.h>
#include <cuda_fp16.h>
#include <cstdint>

// Problem constants
#define KK   27
#define RR   50000
#define CIN  64
#define COUT 64
#define NIN  150000
#define NOUT 150000

#define TILE    128
#define NTILES  ((RR + TILE - 1) / TILE)      // 391
#define TPG     8                             // tiles per block
#define NBX     ((NTILES + TPG - 1) / TPG)    // 49
#define THREADS 256

// SMEM: W(hi) 8K, then 3 stages x 16K (stage = one tile A)
#define OFF_WH  0u
#define OFF_A   8192u
#define STG_SZ  16384u
#define SMEM_BYTES (8192u + 3u * STG_SZ)      // 57344

// ---- global scratch ----------------------------------------------------------
__device__ __align__(16) unsigned short g_xh[(size_t)NIN * 64];    // fp16 x
__device__ __align__(16) unsigned short g_wh[(size_t)KK * 4096];   // fp16 wh swizzled

// ---- helpers -------------------------------------------------------------------
__device__ __forceinline__ uint32_t smem_u32(const void* p) {
    uint32_t a;
    asm("{ .reg .u64 t; cvta.to.shared.u64 t, %1; cvt.u32.u64 %0, t; }" : "=r"(a) : "l"(p));
    return a;
}
__device__ __forceinline__ void ldm4(uint32_t addr, uint32_t& r0, uint32_t& r1,
                                     uint32_t& r2, uint32_t& r3) {
    asm volatile("ldmatrix.sync.aligned.m8n8.x4.shared.b16 {%0,%1,%2,%3}, [%4];"
                 : "=r"(r0), "=r"(r1), "=r"(r2), "=r"(r3) : "r"(addr));
}
__device__ __forceinline__ void mma_f16(float4& d,
                                        uint32_t a0, uint32_t a1, uint32_t a2, uint32_t a3,
                                        uint32_t b0, uint32_t b1) {
    asm volatile("mma.sync.aligned.m16n8k16.row.col.f32.f16.f16.f32 "
                 "{%0,%1,%2,%3}, {%4,%5,%6,%7}, {%8,%9}, {%0,%1,%2,%3};"
                 : "+f"(d.x), "+f"(d.y), "+f"(d.z), "+f"(d.w)
                 : "r"(a0), "r"(a1), "r"(a2), "r"(a3), "r"(b0), "r"(b1));
}
__device__ __forceinline__ void red4(float* p, float a, float b, float c, float d) {
    asm volatile("red.global.add.v4.f32 [%0], {%1, %2, %3, %4};"
                 :: "l"(p), "f"(a), "f"(b), "f"(c), "f"(d) : "memory");
}

// ---- fused precompute: x -> fp16, W -> fp16 swizzled, out = bias -----------------
__global__ void precompute_kernel(const float* __restrict__ x,
                                  const float* __restrict__ w,
                                  const float4* __restrict__ bias4,
                                  float4* __restrict__ out4)
{
    int t = blockIdx.x * blockDim.x + threadIdx.x;

    if (t < NIN * 8) {              // convert x: 8 floats per thread
        int row = t >> 3, c8 = t & 7;
        const float4* p = (const float4*)(x + (size_t)row * 64 + c8 * 8);
        float4 a = p[0], b = p[1];
        float v[8] = {a.x, a.y, a.z, a.w, b.x, b.y, b.z, b.w};
        unsigned short hi[8];
        #pragma unroll
        for (int j = 0; j < 8; j++) {
            __half hh = __float2half_rn(v[j]);
            hi[j] = *reinterpret_cast<unsigned short*>(&hh);
        }
        *(uint4*)(g_xh + (size_t)row * 64 + c8 * 8) = *(uint4*)hi;
    }

    if (t < KK * CIN * COUT) {      // W -> fp16; perm gives SECTOR-CONTIGUOUS red4:
        // thread (tq,h) covers couts {32h+4tq..+3} u {32h+16+4tq..+3}
        // -> each red4 inst writes contiguous 64B (2 full 32B sectors) per row
        int k = t / 4096, rem = t - k * 4096;
        int c = rem >> 6, o = rem & 63;
        __half hh = __float2half_rn(w[t]);
        int H = (o >> 5) & 1, s = (o >> 4) & 1, T = (o >> 2) & 3, u = o & 3;
        int r = 32 * H + 16 * s + 8 * (u >> 1) + 2 * T + (u & 1);
        uint32_t off = (uint32_t)r * 128 + (uint32_t)c * 2;
        uint32_t sw  = off ^ ((off >> 3) & 0x70);
        g_wh[(size_t)k * 4096 + (sw >> 1)] = *reinterpret_cast<unsigned short*>(&hh);
    }

    if (t < NOUT * (COUT / 4)) {    // out = bias broadcast
        out4[t] = bias4[t & (COUT / 4 - 1)];
    }
}

// ---- prefetch 4 rule indices for a tile (this thread's gather slots) -------------
__device__ __forceinline__ void idx_prefetch(int t, int k, const int* __restrict__ in_idx,
                                             int tid, int* idxbuf)
{
    const int gr = tid >> 3;           // row group 0..31
    #pragma unroll
    for (int it = 0; it < 4; it++) {
        int rl = it * 32 + gr;
        int rg = t * TILE + rl;
        idxbuf[it] = (rg < RR) ? __ldg(&in_idx[k * RR + rg]) : -1;
    }
}

// ---- async gather of ONE tile (fp16 rows) using prefetched indices ---------------
__device__ __forceinline__ void gather_tile_buf(uint32_t sbase, int sidx,
                                                const int* idxbuf, int tid)
{
    const int gchunk = tid & 7;        // 16B chunk within 128B row
    const int gr     = tid >> 3;       // row group
    const uint32_t base = sbase + OFF_A + (uint32_t)sidx * STG_SZ;
    #pragma unroll
    for (int it = 0; it < 4; it++) {
        int rl = it * 32 + gr;
        int gi = idxbuf[it];
        if (gi >= 0) {
            const void* src = (const char*)(g_xh + (size_t)gi * 64) + gchunk * 16;
            uint32_t off = (uint32_t)rl * 128 + gchunk * 16;
            uint32_t sw  = off ^ ((off >> 3) & 0x70);
            asm volatile("cp.async.cg.shared.global [%0], [%1], 16;"
                         :: "r"(base + sw), "l"(src) : "memory");
        }
    }
    asm volatile("cp.async.commit_group;" ::: "memory");
}

// ---- main: 256-thr block = one pipeline; 3 blocks/SM; Bh in regs -----------------
extern "C" __global__ void __launch_bounds__(THREADS, 3)
sparse_mma_kernel(const int* __restrict__ in_idx,
                  const int* __restrict__ out_idx,
                  float*     __restrict__ out)
{
    extern __shared__ __align__(1024) char smem[];
    const uint32_t sbase = smem_u32(smem);
    const int tid  = threadIdx.x;
    const int lane = tid & 31;
    const int wrp  = tid >> 5;          // 0..7
    const int k    = blockIdx.y;
    const int tbase = blockIdx.x * TPG;

    int idxbuf[4];

    // prologue: gathers for first 2 tiles, stage W
    idx_prefetch(tbase, k, in_idx, tid, idxbuf);
    gather_tile_buf(sbase, 0, idxbuf, tid);
    idx_prefetch(tbase + 1, k, in_idx, tid, idxbuf);
    gather_tile_buf(sbase, 1, idxbuf, tid);
    // preload indices for tile 2 (issued at loop i=0)
    idx_prefetch(tbase + 2, k, in_idx, tid, idxbuf);
    {
        const uint4* wgp = (const uint4*)(g_wh + (size_t)k * 4096);
        uint4*       wsm = (uint4*)(smem + OFF_WH);
        #pragma unroll
        for (int i = tid; i < 512; i += THREADS) wsm[i] = wgp[i];
    }
    __syncthreads();   // W visible for B-frag ldmatrix

    // warp roles: n-half h, rule-slice s8 (32 rules each)
    const int h   = wrp & 1;
    const int s8  = wrp >> 1;           // 0..3
    const int mrow0 = s8 * 32 + (lane & 15);

    // ---- B fragments (wh): load ONCE into registers ----
    uint32_t Bh[4][8];
    {
        const uint32_t b_xor  = (uint32_t)((lane & 7) << 4);
        const uint32_t b_kofs = (uint32_t)(((lane >> 3) & 1) * 16);
        uint32_t b_rb[2];
        #pragma unroll
        for (int pp = 0; pp < 2; pp++) {
            int p = 2 * h + pp;
            b_rb[pp] = (uint32_t)(((2 * p + (lane >> 4)) * 8 + (lane & 7)) * 128);
        }
        #pragma unroll
        for (int ks = 0; ks < 4; ks++) {
            uint32_t colb = (uint32_t)(32 * ks) + b_kofs;
            #pragma unroll
            for (int pp = 0; pp < 2; pp++)
                ldm4(sbase + OFF_WH + b_rb[pp] + (colb ^ b_xor),
                     Bh[ks][4 * pp], Bh[ks][4 * pp + 1], Bh[ks][4 * pp + 2], Bh[ks][4 * pp + 3]);
        }
    }

    // A ldmatrix addressing (per mb: +16 rows = +2048B)
    const uint32_t a_xor0 = (uint32_t)((mrow0 & 7) << 4);
    const uint32_t a_rb   = (uint32_t)mrow0 * 128u;
    const uint32_t a_kofs = (uint32_t)(((lane >> 4) & 1) * 16);

    // epilogue constants: red4 lanes contiguous -> full 32B sectors
    const int tq    = lane & 3;
    const int rrow  = 32 * s8 + (lane >> 2);
    const int cb1   = 32 * h + 4 * tq;        // couts [cb1, +4) then [cb1+16, +4)

    #pragma unroll 1
    for (int i = 0; i < TPG; i++) {
        int t = tbase + i;

        // wait for this tile's gather, block-wide visibility barrier
        if (i < TPG - 1) asm volatile("cp.async.wait_group 1;" ::: "memory");
        else             asm volatile("cp.async.wait_group 0;" ::: "memory");
        __syncthreads();   // also: block finished reading stage (i-1)%3 last iter

        // issue gather for tile i+2 (indices already in registers)
        if (i + 2 < TPG)
            gather_tile_buf(sbase, (i + 2) % 3, idxbuf, tid);

        // prefetch this tile's 4 output indices (hides under MMA below)
        int obuf[4];
        #pragma unroll
        for (int mb = 0; mb < 2; mb++) {
            int rg1 = t * TILE + rrow + 16 * mb;
            int rg2 = rg1 + 8;
            obuf[2 * mb]     = (rg1 < RR) ? __ldg(&out_idx[k * RR + rg1]) : -1;
            obuf[2 * mb + 1] = (rg2 < RR) ? __ldg(&out_idx[k * RR + rg2]) : -1;
        }
        // prefetch rule indices for tile i+3 (used 2 iterations from now)
        if (i + 3 < TPG)
            idx_prefetch(tbase + i + 3, k, in_idx, tid, idxbuf);

        // ---- MMA with A-frag double buffer over flat (mb,ks) steps ----
        const uint32_t ab = sbase + OFF_A + (uint32_t)(i % 3) * STG_SZ + a_rb;

        uint32_t cur[4], nxt[4];
        {   // load step 0: mb=0, ks=0
            uint32_t cola = a_kofs;
            ldm4(ab + (cola ^ a_xor0), cur[0], cur[1], cur[2], cur[3]);
        }

        #pragma unroll
        for (int mb = 0; mb < 2; mb++) {
            float4 acc[4];
            #pragma unroll
            for (int q = 0; q < 4; q++) acc[q] = make_float4(0.f, 0.f, 0.f, 0.f);

            #pragma unroll
            for (int ks = 0; ks < 4; ks++) {
                // prefetch next step's A frags (next ks, or mb=1 ks=0)
                int step = mb * 4 + ks;
                if (step < 7) {
                    int nmb = (step + 1) >> 2, nks = (step + 1) & 3;
                    uint32_t cola = (uint32_t)(32 * nks) + a_kofs;
                    uint32_t nab  = ab + (uint32_t)nmb * 2048u;
                    ldm4(nab + (cola ^ a_xor0), nxt[0], nxt[1], nxt[2], nxt[3]);
                }
                // 4 HMMA on cur
                #pragma unroll
                for (int q = 0; q < 4; q++)
                    mma_f16(acc[q], cur[0], cur[1], cur[2], cur[3],
                            Bh[ks][2 * q], Bh[ks][2 * q + 1]);
                // rotate
                if (step < 7) {
                    #pragma unroll
                    for (int j = 0; j < 4; j++) cur[j] = nxt[j];
                }
            }

            int o1 = obuf[2 * mb], o2 = obuf[2 * mb + 1];
            if (o1 >= 0) {
                float* b = out + (size_t)o1 * COUT + cb1;
                red4(b,      acc[0].x, acc[0].y, acc[1].x, acc[1].y);
                red4(b + 16, acc[2].x, acc[2].y, acc[3].x, acc[3].y);
            }
            if (o2 >= 0) {
                float* b = out + (size_t)o2 * COUT + cb1;
                red4(b,      acc[0].z, acc[0].w, acc[1].z, acc[1].w);
                red4(b + 16, acc[2].z, acc[2].w, acc[3].z, acc[3].w);
            }
        }
    }
}

extern "C" void kernel_launch(void* const* d_in, const int* in_sizes, int n_in,
                              void* d_out, int out_size)
{
    const float* x       = (const float*)d_in[0];
    const float* w       = (const float*)d_in[1];
    const float* bias    = (const float*)d_in[2];
    const int*   in_idx  = (const int*)d_in[3];
    const int*   out_idx = (const int*)d_in[4];
    float*       out     = (float*)d_out;

    {   // fused: convert x, convert W, out = bias
        int nmax = NOUT * (COUT / 4);   // largest range (2.4M)
        precompute_kernel<<<(nmax + 255) / 256, 256>>>(x, w, (const float4*)bias,
                                                       (float4*)out);
    }

    cudaFuncSetAttribute(sparse_mma_kernel,
                         cudaFuncAttributeMaxDynamicSharedMemorySize, SMEM_BYTES);
    dim3 grid(NBX, KK);
    sparse_mma_kernel<<<grid, THREADS, SMEM_BYTES>>>(in_idx, out_idx, out);
}